// round 1
// baseline (speedup 1.0000x reference)
#include <cuda_runtime.h>

#define NHEAD 12
#define NB    64
#define NTOK  577
#define NC    768
#define ND    64
#define NKEEP 289          // tokens kept incl. CLS
#define NMASK 576
#define MROWS (NB*NTOK)    // 36928
#define QCOLS (3*NC)       // 2304

// ---------------- scratch (static device globals; no allocations) -------------
__device__ __align__(16) float g_q [(size_t)NB*NHEAD*NTOK*ND];   // [B,H,N,D]
__device__ __align__(16) float g_kp[(size_t)NB*NHEAD*NKEEP*ND];  // gathered K
__device__ __align__(16) float g_vp[(size_t)NB*NHEAD*NKEEP*ND];  // gathered V
__device__ __align__(16) float g_ao[(size_t)NB*NTOK*NC];         // attn out [B,N,C]
__device__ int g_dest[NB*NHEAD*NTOK];                            // token -> kept slot (-1 = dropped)

// ---------------- token selection: exact top-288 of 576 per (b,h) -------------
__global__ __launch_bounds__(256) void select_kernel(const float* __restrict__ mask)
{
    int row = blockIdx.x;                       // b*NHEAD + h
    __shared__ float v[NMASK];
    __shared__ unsigned char keep[NMASK];
    const float* mrow = mask + (size_t)row * NMASK;
    for (int i = threadIdx.x; i < NMASK; i += 256) v[i] = mrow[i];
    __syncthreads();
    for (int i = threadIdx.x; i < NMASK; i += 256) {
        float vi = v[i];
        int cnt = 0;
        for (int j = 0; j < NMASK; ++j) {
            float vj = v[j];
            cnt += (vj > vi) || (vj == vi && j < i);   // top_k tie-break: lower index wins
        }
        keep[i] = (cnt < (NKEEP - 1)) ? 1 : 0;
    }
    __syncthreads();
    if (threadIdx.x == 0) {
        int* dm = g_dest + (size_t)row * NTOK;
        dm[0] = 0;                                  // CLS always kept at slot 0
        int pos = 0;
        for (int i = 0; i < NMASK; ++i)
            dm[1 + i] = keep[i] ? (++pos) : -1;     // ascending-index order == sorted idx
    }
}

// ---------------- QKV GEMM (x @ Wqkv + b) with scatter epilogue ---------------
__global__ __launch_bounds__(256) void qkv_gemm(const float* __restrict__ A,
                                                const float* __restrict__ W,
                                                const float* __restrict__ bias)
{
    const int K = NC;
    __shared__ float As[8][132];   // padded: conflict-free transposed store
    __shared__ float Bs[8][128];

    int brow = blockIdx.y * 128;
    int bcol = blockIdx.x * 128;
    int tid  = threadIdx.x;

    int arow = tid >> 1;
    int acol = (tid & 1) << 2;
    int wrow = tid >> 5;
    int wcol = (tid & 31) << 2;
    int ty = tid >> 4, tx = tid & 15;

    float acc[8][8];
    #pragma unroll
    for (int i = 0; i < 8; ++i)
        #pragma unroll
        for (int j = 0; j < 8; ++j) acc[i][j] = 0.f;

    bool arow_ok = (brow + arow) < MROWS;
    const float* Aptr = A + (size_t)(brow + arow) * K + acol;
    const float* Wptr = W + (size_t)wrow * QCOLS + bcol + wcol;

    for (int kt = 0; kt < K; kt += 8) {
        float4 av = arow_ok ? *(const float4*)(Aptr + kt) : make_float4(0.f,0.f,0.f,0.f);
        float4 wv = *(const float4*)(Wptr + (size_t)kt * QCOLS);
        As[acol+0][arow] = av.x;
        As[acol+1][arow] = av.y;
        As[acol+2][arow] = av.z;
        As[acol+3][arow] = av.w;
        *(float4*)&Bs[wrow][wcol] = wv;
        __syncthreads();
        #pragma unroll
        for (int k = 0; k < 8; ++k) {
            float ar[8], br[8];
            *(float4*)&ar[0] = *(const float4*)&As[k][ty*8];
            *(float4*)&ar[4] = *(const float4*)&As[k][ty*8+4];
            *(float4*)&br[0] = *(const float4*)&Bs[k][tx*8];
            *(float4*)&br[4] = *(const float4*)&Bs[k][tx*8+4];
            #pragma unroll
            for (int i = 0; i < 8; ++i)
                #pragma unroll
                for (int j = 0; j < 8; ++j)
                    acc[i][j] = fmaf(ar[i], br[j], acc[i][j]);
        }
        __syncthreads();
    }

    // epilogue: c0..c0+7 live in one (s,h) because c0 is a multiple of 8
    int c0 = bcol + tx * 8;
    int s  = c0 / NC;
    int hd = c0 - s * NC;
    int h  = hd >> 6;
    int d0 = hd & 63;
    float bv[8];
    *(float4*)&bv[0] = *(const float4*)(bias + c0);
    *(float4*)&bv[4] = *(const float4*)(bias + c0 + 4);

    #pragma unroll
    for (int i = 0; i < 8; ++i) {
        int m = brow + ty * 8 + i;
        if (m >= MROWS) continue;
        int b = m / NTOK;
        int n = m - b * NTOK;
        int bh = b * NHEAD + h;
        float t[8];
        #pragma unroll
        for (int j = 0; j < 8; ++j) t[j] = acc[i][j] + bv[j];
        if (s == 0) {
            float* dst = &g_q[((size_t)bh * NTOK + n) * ND + d0];
            *(float4*)(dst)     = make_float4(t[0], t[1], t[2], t[3]);
            *(float4*)(dst + 4) = make_float4(t[4], t[5], t[6], t[7]);
        } else {
            int dest = g_dest[bh * NTOK + n];
            if (dest >= 0) {
                float* base = (s == 1) ? g_kp : g_vp;
                float* dst = &base[((size_t)bh * NKEEP + dest) * ND + d0];
                *(float4*)(dst)     = make_float4(t[0], t[1], t[2], t[3]);
                *(float4*)(dst + 4) = make_float4(t[4], t[5], t[6], t[7]);
            }
        }
    }
}

// ---------------- attention: one CTA per (b,h, 32-query tile) -----------------
// SMEM: Qs[32*64] | Vs[289*64] | Ss[32*292] | Ks[289*65]  (Ks last: odd stride)
#define SS_STRIDE 292
#define KS_STRIDE 65
__global__ __launch_bounds__(256) void attn_kernel()
{
    extern __shared__ float sh[];
    float* Qs = sh;                       // 2048
    float* Vs = Qs + 32 * ND;             // 18496
    float* Ss = Vs + NKEEP * ND;          // 9344
    float* Ks = Ss + 32 * SS_STRIDE;      // 18785

    int tid = threadIdx.x;
    int bh  = blockIdx.y;
    int q0  = blockIdx.x * 32;

    const float* kp = g_kp + (size_t)bh * NKEEP * ND;
    const float* vp = g_vp + (size_t)bh * NKEEP * ND;
    for (int idx = tid; idx < NKEEP * ND; idx += 256) {
        int m = idx >> 6, d = idx & 63;
        Ks[m * KS_STRIDE + d] = kp[idx];
        Vs[idx] = vp[idx];
    }
    const float* qp = g_q + (size_t)bh * NTOK * ND;
    for (int idx = tid; idx < 32 * ND; idx += 256) {
        int qq = idx >> 6;
        int qg = q0 + qq;
        Qs[idx] = (qg < NTOK) ? qp[(size_t)qg * ND + (idx & 63)] : 0.f;
    }
    __syncthreads();

    // Phase A: S = (Q K^T) * scale, 4x4 register tiles
    {
        int ty = tid >> 5, tx = tid & 31;
        #pragma unroll
        for (int pass = 0; pass < 3; ++pass) {
            int mb = pass * 128;
            int moff[4]; bool mv[4];
            #pragma unroll
            for (int j = 0; j < 4; ++j) {
                int m = mb + tx + 32 * j;
                mv[j] = (m < NKEEP);
                moff[j] = mv[j] ? m * KS_STRIDE : 0;
            }
            float acc[4][4];
            #pragma unroll
            for (int i = 0; i < 4; ++i)
                #pragma unroll
                for (int j = 0; j < 4; ++j) acc[i][j] = 0.f;
            for (int kk = 0; kk < ND; ++kk) {
                float a[4], b[4];
                #pragma unroll
                for (int i = 0; i < 4; ++i) a[i] = Qs[(ty * 4 + i) * ND + kk];
                #pragma unroll
                for (int j = 0; j < 4; ++j) b[j] = Ks[moff[j] + kk];
                #pragma unroll
                for (int i = 0; i < 4; ++i)
                    #pragma unroll
                    for (int j = 0; j < 4; ++j)
                        acc[i][j] = fmaf(a[i], b[j], acc[i][j]);
            }
            #pragma unroll
            for (int j = 0; j < 4; ++j) {
                if (!mv[j]) continue;
                int m = mb + tx + 32 * j;
                #pragma unroll
                for (int i = 0; i < 4; ++i)
                    Ss[(ty * 4 + i) * SS_STRIDE + m] = acc[i][j] * 0.125f;
            }
        }
    }
    __syncthreads();

    // Phase B: row softmax (one warp per 4 rows)
    {
        int w = tid >> 5, lane = tid & 31;
        #pragma unroll
        for (int r = 0; r < 4; ++r) {
            float* Sr = Ss + (w * 4 + r) * SS_STRIDE;
            float mx = -3.0e38f;
            for (int m = lane; m < NKEEP; m += 32) mx = fmaxf(mx, Sr[m]);
            #pragma unroll
            for (int o = 16; o; o >>= 1) mx = fmaxf(mx, __shfl_xor_sync(0xffffffffu, mx, o));
            float sum = 0.f;
            for (int m = lane; m < NKEEP; m += 32) {
                float e = __expf(Sr[m] - mx);
                Sr[m] = e;
                sum += e;
            }
            #pragma unroll
            for (int o = 16; o; o >>= 1) sum += __shfl_xor_sync(0xffffffffu, sum, o);
            float inv = 1.f / sum;
            for (int m = lane; m < NKEEP; m += 32) Sr[m] *= inv;
        }
    }
    __syncthreads();

    // Phase C: O = P @ V, 2 queries x 4 dims per thread
    {
        int tx = tid & 15, ty = tid >> 4;
        float o0x=0.f,o0y=0.f,o0z=0.f,o0w=0.f;
        float o1x=0.f,o1y=0.f,o1z=0.f,o1w=0.f;
        int ql = ty * 2;
        const float* S0 = Ss + ql * SS_STRIDE;
        const float* S1 = S0 + SS_STRIDE;
        for (int m = 0; m < NKEEP; ++m) {
            float p0 = S0[m];
            float p1 = S1[m];
            float4 v = *(const float4*)&Vs[m * ND + tx * 4];
            o0x = fmaf(p0, v.x, o0x); o0y = fmaf(p0, v.y, o0y);
            o0z = fmaf(p0, v.z, o0z); o0w = fmaf(p0, v.w, o0w);
            o1x = fmaf(p1, v.x, o1x); o1y = fmaf(p1, v.y, o1y);
            o1z = fmaf(p1, v.z, o1z); o1w = fmaf(p1, v.w, o1w);
        }
        int b = bh / NHEAD, h = bh - b * NHEAD;
        int qg = q0 + ql;
        if (qg < NTOK)
            *(float4*)&g_ao[((size_t)(b * NTOK + qg)) * NC + h * ND + tx * 4]
                = make_float4(o0x, o0y, o0z, o0w);
        if (qg + 1 < NTOK)
            *(float4*)&g_ao[((size_t)(b * NTOK + qg + 1)) * NC + h * ND + tx * 4]
                = make_float4(o1x, o1y, o1z, o1w);
    }
}

// ---------------- projection GEMM (g_ao @ Wproj + b) --------------------------
__global__ __launch_bounds__(256) void proj_gemm(const float* __restrict__ W,
                                                 const float* __restrict__ bias,
                                                 float* __restrict__ out)
{
    const int K = NC;
    __shared__ float As[8][132];
    __shared__ float Bs[8][128];

    int brow = blockIdx.y * 128;
    int bcol = blockIdx.x * 128;
    int tid  = threadIdx.x;

    int arow = tid >> 1;
    int acol = (tid & 1) << 2;
    int wrow = tid >> 5;
    int wcol = (tid & 31) << 2;
    int ty = tid >> 4, tx = tid & 15;

    float acc[8][8];
    #pragma unroll
    for (int i = 0; i < 8; ++i)
        #pragma unroll
        for (int j = 0; j < 8; ++j) acc[i][j] = 0.f;

    bool arow_ok = (brow + arow) < MROWS;
    const float* Aptr = g_ao + (size_t)(brow + arow) * K + acol;
    const float* Wptr = W + (size_t)wrow * NC + bcol + wcol;

    for (int kt = 0; kt < K; kt += 8) {
        float4 av = arow_ok ? *(const float4*)(Aptr + kt) : make_float4(0.f,0.f,0.f,0.f);
        float4 wv = *(const float4*)(Wptr + (size_t)kt * NC);
        As[acol+0][arow] = av.x;
        As[acol+1][arow] = av.y;
        As[acol+2][arow] = av.z;
        As[acol+3][arow] = av.w;
        *(float4*)&Bs[wrow][wcol] = wv;
        __syncthreads();
        #pragma unroll
        for (int k = 0; k < 8; ++k) {
            float ar[8], br[8];
            *(float4*)&ar[0] = *(const float4*)&As[k][ty*8];
            *(float4*)&ar[4] = *(const float4*)&As[k][ty*8+4];
            *(float4*)&br[0] = *(const float4*)&Bs[k][tx*8];
            *(float4*)&br[4] = *(const float4*)&Bs[k][tx*8+4];
            #pragma unroll
            for (int i = 0; i < 8; ++i)
                #pragma unroll
                for (int j = 0; j < 8; ++j)
                    acc[i][j] = fmaf(ar[i], br[j], acc[i][j]);
        }
        __syncthreads();
    }

    int c0 = bcol + tx * 8;
    float bv[8];
    *(float4*)&bv[0] = *(const float4*)(bias + c0);
    *(float4*)&bv[4] = *(const float4*)(bias + c0 + 4);

    #pragma unroll
    for (int i = 0; i < 8; ++i) {
        int m = brow + ty * 8 + i;
        if (m >= MROWS) continue;
        float t[8];
        #pragma unroll
        for (int j = 0; j < 8; ++j) t[j] = acc[i][j] + bv[j];
        float* dst = out + (size_t)m * NC + c0;
        *(float4*)(dst)     = make_float4(t[0], t[1], t[2], t[3]);
        *(float4*)(dst + 4) = make_float4(t[4], t[5], t[6], t[7]);
    }
}

// ---------------- launch -------------------------------------------------------
extern "C" void kernel_launch(void* const* d_in, const int* in_sizes, int n_in,
                              void* d_out, int out_size)
{
    const float* x     = (const float*)d_in[0];
    const float* mask  = (const float*)d_in[1];
    const float* Wqkv  = (const float*)d_in[2];
    const float* bqkv  = (const float*)d_in[3];
    const float* Wproj = (const float*)d_in[4];
    const float* bproj = (const float*)d_in[5];
    float* out = (float*)d_out;

    select_kernel<<<NB * NHEAD, 256>>>(mask);

    dim3 g1(QCOLS / 128, (MROWS + 127) / 128);
    qkv_gemm<<<g1, 256>>>(x, Wqkv, bqkv);

    size_t smem = (size_t)(32*ND + NKEEP*ND + 32*SS_STRIDE + NKEEP*KS_STRIDE) * sizeof(float);
    cudaFuncSetAttribute(attn_kernel, cudaFuncAttributeMaxDynamicSharedMemorySize, (int)smem);
    attn_kernel<<<dim3((NTOK + 31) / 32, NB * NHEAD), 256, smem>>>();

    dim3 g2(NC / 128, (MROWS + 127) / 128);
    proj_gemm<<<g2, 256>>>(Wproj, bproj, out);
}

// round 3
// speedup vs baseline: 1.0516x; 1.0516x over previous
#include <cuda_runtime.h>

#define NHEAD 12
#define NB    64
#define NTOK  577
#define NC    768
#define ND    64
#define NKEEP 289          // tokens kept incl. CLS
#define NMASK 576
#define MROWS (NB*NTOK)    // 36928
#define QCOLS (3*NC)       // 2304

// ---------------- scratch (static device globals; no allocations) -------------
__device__ __align__(16) float g_q [(size_t)NB*NHEAD*NTOK*ND];   // [B,H,N,D]
__device__ __align__(16) float g_kp[(size_t)NB*NHEAD*NKEEP*ND];  // gathered K
__device__ __align__(16) float g_vp[(size_t)NB*NHEAD*NKEEP*ND];  // gathered V
__device__ __align__(16) float g_ao[(size_t)NB*NTOK*NC];         // attn out [B,N,C]
__device__ int g_dest[NB*NHEAD*NTOK];                            // token -> kept slot (-1 = dropped)

// ---------------- token selection: exact top-288 of 576 per (b,h) -------------
__global__ __launch_bounds__(256) void select_kernel(const float* __restrict__ mask)
{
    int row = blockIdx.x;                       // b*NHEAD + h
    __shared__ float v[NMASK];
    __shared__ unsigned char keep[NMASK];
    const float* mrow = mask + (size_t)row * NMASK;
    for (int i = threadIdx.x; i < NMASK; i += 256) v[i] = mrow[i];
    __syncthreads();
    for (int i = threadIdx.x; i < NMASK; i += 256) {
        float vi = v[i];
        int cnt = 0;
        for (int j = 0; j < NMASK; ++j) {
            float vj = v[j];
            cnt += (vj > vi) || (vj == vi && j < i);   // top_k tie-break: lower index wins
        }
        keep[i] = (cnt < (NKEEP - 1)) ? 1 : 0;
    }
    __syncthreads();
    if (threadIdx.x == 0) {
        int* dm = g_dest + (size_t)row * NTOK;
        dm[0] = 0;                                  // CLS always kept at slot 0
        int pos = 0;
        for (int i = 0; i < NMASK; ++i)
            dm[1 + i] = keep[i] ? (++pos) : -1;     // ascending-index order == sorted idx
    }
}

// ---------------- 128x128x16 SGEMM, double-buffered smem, reg prefetch --------
// LDW: leading dim of W (and of C). SCATTER: QKV scatter epilogue vs plain.
// USE_AO: read A from the device-global g_ao (device-side symbol access —
//         cannot be passed as a host-side kernel argument).
template<int LDW, bool SCATTER, bool USE_AO>
__global__ __launch_bounds__(256, 2) void gemm128(const float* __restrict__ Ain,
                                                  const float* __restrict__ W,
                                                  const float* __restrict__ bias,
                                                  float* __restrict__ out)
{
    const float* __restrict__ A = USE_AO ? (const float*)g_ao : Ain;
    __shared__ float As[2][16][132];   // [stage][k][m], padded
    __shared__ float Bs[2][16][128];   // [stage][k][n]
    const int K = NC;

    int tid  = threadIdx.x;
    int brow = blockIdx.y * 128;
    int bcol = blockIdx.x * 128;

    int ar0 = tid >> 2;          // 0..63 (rows ar0, ar0+64)
    int ac  = (tid & 3) << 2;    // k-offset 0,4,8,12
    int br0 = tid >> 5;          // 0..7  (rows br0, br0+8)
    int bc  = (tid & 31) << 2;   // col offset
    int ty  = tid >> 4, tx = tid & 15;

    bool aok0 = (brow + ar0)      < MROWS;
    bool aok1 = (brow + ar0 + 64) < MROWS;
    const float* Ap0 = A + (size_t)(brow + ar0) * K + ac;
    const float* Ap1 = Ap0 + (size_t)64 * K;
    const float* Wp  = W + (size_t)br0 * LDW + bcol + bc;

    const float4 z4 = make_float4(0.f, 0.f, 0.f, 0.f);
    float4 pa0 = aok0 ? *(const float4*)Ap0 : z4;
    float4 pa1 = aok1 ? *(const float4*)Ap1 : z4;
    float4 pb0 = *(const float4*)Wp;
    float4 pb1 = *(const float4*)(Wp + (size_t)8 * LDW);

    As[0][ac+0][ar0] = pa0.x; As[0][ac+1][ar0] = pa0.y;
    As[0][ac+2][ar0] = pa0.z; As[0][ac+3][ar0] = pa0.w;
    As[0][ac+0][ar0+64] = pa1.x; As[0][ac+1][ar0+64] = pa1.y;
    As[0][ac+2][ar0+64] = pa1.z; As[0][ac+3][ar0+64] = pa1.w;
    *(float4*)&Bs[0][br0][bc]   = pb0;
    *(float4*)&Bs[0][br0+8][bc] = pb1;
    __syncthreads();

    float acc[8][8];
    #pragma unroll
    for (int i = 0; i < 8; ++i)
        #pragma unroll
        for (int j = 0; j < 8; ++j) acc[i][j] = 0.f;

    int buf = 0;
    for (int kt = 16; kt <= K; kt += 16) {
        bool more = kt < K;
        if (more) {
            pa0 = aok0 ? *(const float4*)(Ap0 + kt) : z4;
            pa1 = aok1 ? *(const float4*)(Ap1 + kt) : z4;
            pb0 = *(const float4*)(Wp + (size_t)kt * LDW);
            pb1 = *(const float4*)(Wp + (size_t)(kt + 8) * LDW);
        }
        #pragma unroll
        for (int k = 0; k < 16; ++k) {
            float ar[8], br[8];
            *(float4*)&ar[0] = *(const float4*)&As[buf][k][ty*8];
            *(float4*)&ar[4] = *(const float4*)&As[buf][k][ty*8+4];
            *(float4*)&br[0] = *(const float4*)&Bs[buf][k][tx*8];
            *(float4*)&br[4] = *(const float4*)&Bs[buf][k][tx*8+4];
            #pragma unroll
            for (int i = 0; i < 8; ++i)
                #pragma unroll
                for (int j = 0; j < 8; ++j)
                    acc[i][j] = fmaf(ar[i], br[j], acc[i][j]);
        }
        if (more) {
            int nb = buf ^ 1;
            As[nb][ac+0][ar0] = pa0.x; As[nb][ac+1][ar0] = pa0.y;
            As[nb][ac+2][ar0] = pa0.z; As[nb][ac+3][ar0] = pa0.w;
            As[nb][ac+0][ar0+64] = pa1.x; As[nb][ac+1][ar0+64] = pa1.y;
            As[nb][ac+2][ar0+64] = pa1.z; As[nb][ac+3][ar0+64] = pa1.w;
            *(float4*)&Bs[nb][br0][bc]   = pb0;
            *(float4*)&Bs[nb][br0+8][bc] = pb1;
            __syncthreads();
            buf = nb;
        }
    }

    // ---------------- epilogue ----------------
    int c0 = bcol + tx * 8;
    float bv[8];
    *(float4*)&bv[0] = *(const float4*)(bias + c0);
    *(float4*)&bv[4] = *(const float4*)(bias + c0 + 4);

    if (SCATTER) {
        // c0..c0+7 stay within one (s,h) because c0 is a multiple of 8
        int s  = c0 / NC;
        int hd = c0 - s * NC;
        int h  = hd >> 6;
        int d0 = hd & 63;
        #pragma unroll
        for (int i = 0; i < 8; ++i) {
            int m = brow + ty * 8 + i;
            if (m >= MROWS) continue;
            int b = m / NTOK;
            int n = m - b * NTOK;
            int bh = b * NHEAD + h;
            float t[8];
            #pragma unroll
            for (int j = 0; j < 8; ++j) t[j] = acc[i][j] + bv[j];
            if (s == 0) {
                float* dst = &g_q[((size_t)bh * NTOK + n) * ND + d0];
                *(float4*)(dst)     = make_float4(t[0], t[1], t[2], t[3]);
                *(float4*)(dst + 4) = make_float4(t[4], t[5], t[6], t[7]);
            } else {
                int dest = g_dest[bh * NTOK + n];
                if (dest >= 0) {
                    float* base = (s == 1) ? g_kp : g_vp;
                    float* dst = &base[((size_t)bh * NKEEP + dest) * ND + d0];
                    *(float4*)(dst)     = make_float4(t[0], t[1], t[2], t[3]);
                    *(float4*)(dst + 4) = make_float4(t[4], t[5], t[6], t[7]);
                }
            }
        }
    } else {
        #pragma unroll
        for (int i = 0; i < 8; ++i) {
            int m = brow + ty * 8 + i;
            if (m >= MROWS) continue;
            float t[8];
            #pragma unroll
            for (int j = 0; j < 8; ++j) t[j] = acc[i][j] + bv[j];
            float* dst = out + (size_t)m * LDW + c0;
            *(float4*)(dst)     = make_float4(t[0], t[1], t[2], t[3]);
            *(float4*)(dst + 4) = make_float4(t[4], t[5], t[6], t[7]);
        }
    }
}

// ---------------- attention: one CTA per (b,h, 32-query tile) -----------------
// SMEM: Qs[32*64] | Vs[289*64] | Ss[32*292] | Ks[289*65]  (Ks last: odd stride)
#define SS_STRIDE 292
#define KS_STRIDE 65
__global__ __launch_bounds__(256) void attn_kernel()
{
    extern __shared__ float sh[];
    float* Qs = sh;                       // 2048
    float* Vs = Qs + 32 * ND;             // 18496
    float* Ss = Vs + NKEEP * ND;          // 9344
    float* Ks = Ss + 32 * SS_STRIDE;      // 18785

    int tid = threadIdx.x;
    int bh  = blockIdx.y;
    int q0  = blockIdx.x * 32;

    const float* kp = g_kp + (size_t)bh * NKEEP * ND;
    const float* vp = g_vp + (size_t)bh * NKEEP * ND;
    for (int idx = tid; idx < NKEEP * ND; idx += 256) {
        int m = idx >> 6, d = idx & 63;
        Ks[m * KS_STRIDE + d] = kp[idx];
        Vs[idx] = vp[idx];
    }
    const float* qp = g_q + (size_t)bh * NTOK * ND;
    for (int idx = tid; idx < 32 * ND; idx += 256) {
        int qq = idx >> 6;
        int qg = q0 + qq;
        Qs[idx] = (qg < NTOK) ? qp[(size_t)qg * ND + (idx & 63)] : 0.f;
    }
    __syncthreads();

    // Phase A: S = (Q K^T) * scale, 4x4 register tiles
    {
        int ty = tid >> 5, tx = tid & 31;
        #pragma unroll
        for (int pass = 0; pass < 3; ++pass) {
            int mb = pass * 128;
            int moff[4]; bool mv[4];
            #pragma unroll
            for (int j = 0; j < 4; ++j) {
                int m = mb + tx + 32 * j;
                mv[j] = (m < NKEEP);
                moff[j] = mv[j] ? m * KS_STRIDE : 0;
            }
            float acc[4][4];
            #pragma unroll
            for (int i = 0; i < 4; ++i)
                #pragma unroll
                for (int j = 0; j < 4; ++j) acc[i][j] = 0.f;
            for (int kk = 0; kk < ND; ++kk) {
                float a[4], b[4];
                #pragma unroll
                for (int i = 0; i < 4; ++i) a[i] = Qs[(ty * 4 + i) * ND + kk];
                #pragma unroll
                for (int j = 0; j < 4; ++j) b[j] = Ks[moff[j] + kk];
                #pragma unroll
                for (int i = 0; i < 4; ++i)
                    #pragma unroll
                    for (int j = 0; j < 4; ++j)
                        acc[i][j] = fmaf(a[i], b[j], acc[i][j]);
            }
            #pragma unroll
            for (int j = 0; j < 4; ++j) {
                if (!mv[j]) continue;
                int m = mb + tx + 32 * j;
                #pragma unroll
                for (int i = 0; i < 4; ++i)
                    Ss[(ty * 4 + i) * SS_STRIDE + m] = acc[i][j] * 0.125f;
            }
        }
    }
    __syncthreads();

    // Phase B: row softmax (one warp per 4 rows)
    {
        int w = tid >> 5, lane = tid & 31;
        #pragma unroll
        for (int r = 0; r < 4; ++r) {
            float* Sr = Ss + (w * 4 + r) * SS_STRIDE;
            float mx = -3.0e38f;
            for (int m = lane; m < NKEEP; m += 32) mx = fmaxf(mx, Sr[m]);
            #pragma unroll
            for (int o = 16; o; o >>= 1) mx = fmaxf(mx, __shfl_xor_sync(0xffffffffu, mx, o));
            float sum = 0.f;
            for (int m = lane; m < NKEEP; m += 32) {
                float e = __expf(Sr[m] - mx);
                Sr[m] = e;
                sum += e;
            }
            #pragma unroll
            for (int o = 16; o; o >>= 1) sum += __shfl_xor_sync(0xffffffffu, sum, o);
            float inv = 1.f / sum;
            for (int m = lane; m < NKEEP; m += 32) Sr[m] *= inv;
        }
    }
    __syncthreads();

    // Phase C: O = P @ V, 2 queries x 4 dims per thread
    {
        int tx = tid & 15, ty = tid >> 4;
        float o0x=0.f,o0y=0.f,o0z=0.f,o0w=0.f;
        float o1x=0.f,o1y=0.f,o1z=0.f,o1w=0.f;
        int ql = ty * 2;
        const float* S0 = Ss + ql * SS_STRIDE;
        const float* S1 = S0 + SS_STRIDE;
        for (int m = 0; m < NKEEP; ++m) {
            float p0 = S0[m];
            float p1 = S1[m];
            float4 v = *(const float4*)&Vs[m * ND + tx * 4];
            o0x = fmaf(p0, v.x, o0x); o0y = fmaf(p0, v.y, o0y);
            o0z = fmaf(p0, v.z, o0z); o0w = fmaf(p0, v.w, o0w);
            o1x = fmaf(p1, v.x, o1x); o1y = fmaf(p1, v.y, o1y);
            o1z = fmaf(p1, v.z, o1z); o1w = fmaf(p1, v.w, o1w);
        }
        int b = bh / NHEAD, h = bh - b * NHEAD;
        int qg = q0 + ql;
        if (qg < NTOK)
            *(float4*)&g_ao[((size_t)(b * NTOK + qg)) * NC + h * ND + tx * 4]
                = make_float4(o0x, o0y, o0z, o0w);
        if (qg + 1 < NTOK)
            *(float4*)&g_ao[((size_t)(b * NTOK + qg + 1)) * NC + h * ND + tx * 4]
                = make_float4(o1x, o1y, o1z, o1w);
    }
}

// ---------------- launch -------------------------------------------------------
extern "C" void kernel_launch(void* const* d_in, const int* in_sizes, int n_in,
                              void* d_out, int out_size)
{
    const float* x     = (const float*)d_in[0];
    const float* mask  = (const float*)d_in[1];
    const float* Wqkv  = (const float*)d_in[2];
    const float* bqkv  = (const float*)d_in[3];
    const float* Wproj = (const float*)d_in[4];
    const float* bproj = (const float*)d_in[5];
    float* out = (float*)d_out;

    select_kernel<<<NB * NHEAD, 256>>>(mask);

    dim3 g1(QCOLS / 128, (MROWS + 127) / 128);
    gemm128<QCOLS, true, false><<<g1, 256>>>(x, Wqkv, bqkv, nullptr);

    size_t smem = (size_t)(32*ND + NKEEP*ND + 32*SS_STRIDE + NKEEP*KS_STRIDE) * sizeof(float);
    cudaFuncSetAttribute(attn_kernel, cudaFuncAttributeMaxDynamicSharedMemorySize, (int)smem);
    attn_kernel<<<dim3((NTOK + 31) / 32, NB * NHEAD), 256, smem>>>();

    dim3 g2(NC / 128, (MROWS + 127) / 128);
    gemm128<NC, false, true><<<g2, 256>>>(nullptr, Wproj, bproj, out);
}

// round 5
// speedup vs baseline: 1.5696x; 1.4927x over previous
#include <cuda_runtime.h>
#include <cstdint>

#define NHEAD 12
#define NB    64
#define NTOK  577
#define NC    768
#define ND    64
#define NKEEP 289          // tokens kept incl. CLS
#define NMASK 576
#define MROWS (NB*NTOK)    // 36928
#define QCOLS (3*NC)       // 2304

// ---------------- scratch (static device globals; no allocations) -------------
__device__ __align__(16) float g_q [(size_t)NB*NHEAD*NTOK*ND];   // [B,H,N,D]
__device__ __align__(16) float g_kp[(size_t)NB*NHEAD*NKEEP*ND];  // gathered K
__device__ __align__(16) float g_vp[(size_t)NB*NHEAD*NKEEP*ND];  // gathered V
__device__ __align__(16) float g_ao[(size_t)NB*NTOK*NC];         // attn out [B,N,C]
__device__ int g_dest[NB*NHEAD*NTOK];                            // token -> kept slot (-1 = dropped)

// ---------------- helpers ------------------------------------------------------
__device__ __forceinline__ float tf32_rna(float v) {
    uint32_t u;
    asm("cvt.rna.tf32.f32 %0, %1;" : "=r"(u) : "f"(v));
    return __uint_as_float(u);
}
__device__ __forceinline__ void mma_tf32(float* c, const uint32_t* a, const uint32_t* b) {
    asm volatile(
        "mma.sync.aligned.m16n8k8.row.col.f32.tf32.tf32.f32 "
        "{%0,%1,%2,%3}, {%4,%5,%6,%7}, {%8,%9}, {%0,%1,%2,%3};\n"
        : "+f"(c[0]), "+f"(c[1]), "+f"(c[2]), "+f"(c[3])
        : "r"(a[0]), "r"(a[1]), "r"(a[2]), "r"(a[3]), "r"(b[0]), "r"(b[1]));
}

// ---------------- token selection: exact top-288 of 576 per (b,h) -------------
__global__ __launch_bounds__(256) void select_kernel(const float* __restrict__ mask)
{
    int row = blockIdx.x;                       // b*NHEAD + h
    __shared__ float v[NMASK];
    __shared__ unsigned char keep[NMASK];
    const float* mrow = mask + (size_t)row * NMASK;
    for (int i = threadIdx.x; i < NMASK; i += 256) v[i] = mrow[i];
    __syncthreads();
    for (int i = threadIdx.x; i < NMASK; i += 256) {
        float vi = v[i];
        int cnt = 0;
        for (int j = 0; j < NMASK; ++j) {
            float vj = v[j];
            cnt += (vj > vi) || (vj == vi && j < i);   // top_k tie-break: lower index wins
        }
        keep[i] = (cnt < (NKEEP - 1)) ? 1 : 0;
    }
    __syncthreads();
    if (threadIdx.x == 0) {
        int* dm = g_dest + (size_t)row * NTOK;
        dm[0] = 0;
        int pos = 0;
        for (int i = 0; i < NMASK; ++i)
            dm[1 + i] = keep[i] ? (++pos) : -1;
    }
}

// ---------------- 128x128x16 tf32 mma.sync GEMM, double-buffered smem ----------
// As[k][m] (k-major) feeds A fragments directly; Bs[k][n] is the .col B source.
// LDW: leading dim of W/C. SCATTER: qkv scatter epilogue. USE_AO: A = g_ao.
template<int LDW, bool SCATTER, bool USE_AO>
__global__ __launch_bounds__(256, 2) void gemm_mma(const float* __restrict__ Ain,
                                                   const float* __restrict__ W,
                                                   const float* __restrict__ bias,
                                                   float* __restrict__ out)
{
    const float* __restrict__ A = USE_AO ? (const float*)g_ao : Ain;
    __shared__ float As[2][16][132];   // [stage][k][m], padded
    __shared__ float Bs[2][16][132];   // [stage][k][n], padded
    const int K = NC;

    int tid  = threadIdx.x;
    int brow = blockIdx.y * 128;
    int bcol = blockIdx.x * 128;

    // loader coords (same as R3)
    int ar0 = tid >> 2;          // 0..63 (rows ar0, ar0+64)
    int ac  = (tid & 3) << 2;    // k-offset 0,4,8,12
    int br0 = tid >> 5;          // 0..7  (k rows br0, br0+8)
    int bc  = (tid & 31) << 2;   // col offset

    // mma coords
    int wid  = tid >> 5;
    int lane = tid & 31;
    int gid  = lane >> 2;        // 0..7
    int tid4 = lane & 3;         // 0..3
    int m0 = (wid >> 2) * 64;    // warp m origin (0 or 64)
    int n0 = (wid & 3) * 32;     // warp n origin

    bool aok0 = (brow + ar0)      < MROWS;
    bool aok1 = (brow + ar0 + 64) < MROWS;
    const float* Ap0 = A + (size_t)(brow + ar0) * K + ac;
    const float* Ap1 = Ap0 + (size_t)64 * K;
    const float* Wp  = W + (size_t)br0 * LDW + bcol + bc;

    const float4 z4 = make_float4(0.f, 0.f, 0.f, 0.f);
    float4 pa0 = aok0 ? *(const float4*)Ap0 : z4;
    float4 pa1 = aok1 ? *(const float4*)Ap1 : z4;
    float4 pb0 = *(const float4*)Wp;
    float4 pb1 = *(const float4*)(Wp + (size_t)8 * LDW);

    As[0][ac+0][ar0] = tf32_rna(pa0.x); As[0][ac+1][ar0] = tf32_rna(pa0.y);
    As[0][ac+2][ar0] = tf32_rna(pa0.z); As[0][ac+3][ar0] = tf32_rna(pa0.w);
    As[0][ac+0][ar0+64] = tf32_rna(pa1.x); As[0][ac+1][ar0+64] = tf32_rna(pa1.y);
    As[0][ac+2][ar0+64] = tf32_rna(pa1.z); As[0][ac+3][ar0+64] = tf32_rna(pa1.w);
    Bs[0][br0][bc+0]   = tf32_rna(pb0.x); Bs[0][br0][bc+1]   = tf32_rna(pb0.y);
    Bs[0][br0][bc+2]   = tf32_rna(pb0.z); Bs[0][br0][bc+3]   = tf32_rna(pb0.w);
    Bs[0][br0+8][bc+0] = tf32_rna(pb1.x); Bs[0][br0+8][bc+1] = tf32_rna(pb1.y);
    Bs[0][br0+8][bc+2] = tf32_rna(pb1.z); Bs[0][br0+8][bc+3] = tf32_rna(pb1.w);
    __syncthreads();

    float c[4][4][4];
    #pragma unroll
    for (int mt = 0; mt < 4; ++mt)
        #pragma unroll
        for (int nt = 0; nt < 4; ++nt)
            #pragma unroll
            for (int r = 0; r < 4; ++r) c[mt][nt][r] = 0.f;

    int buf = 0;
    for (int kt = 16; kt <= K; kt += 16) {
        bool more = kt < K;
        if (more) {
            pa0 = aok0 ? *(const float4*)(Ap0 + kt) : z4;
            pa1 = aok1 ? *(const float4*)(Ap1 + kt) : z4;
            pb0 = *(const float4*)(Wp + (size_t)kt * LDW);
            pb1 = *(const float4*)(Wp + (size_t)(kt + 8) * LDW);
        }
        #pragma unroll
        for (int ks = 0; ks < 2; ++ks) {
            const int kb = ks * 8;
            uint32_t bf[4][2], af[4][4];
            #pragma unroll
            for (int nt = 0; nt < 4; ++nt) {
                bf[nt][0] = __float_as_uint(Bs[buf][kb + tid4][n0 + nt*8 + gid]);
                bf[nt][1] = __float_as_uint(Bs[buf][kb + tid4 + 4][n0 + nt*8 + gid]);
            }
            #pragma unroll
            for (int mt = 0; mt < 4; ++mt) {
                af[mt][0] = __float_as_uint(As[buf][kb + tid4][m0 + mt*16 + gid]);
                af[mt][1] = __float_as_uint(As[buf][kb + tid4][m0 + mt*16 + gid + 8]);
                af[mt][2] = __float_as_uint(As[buf][kb + tid4 + 4][m0 + mt*16 + gid]);
                af[mt][3] = __float_as_uint(As[buf][kb + tid4 + 4][m0 + mt*16 + gid + 8]);
            }
            #pragma unroll
            for (int mt = 0; mt < 4; ++mt)
                #pragma unroll
                for (int nt = 0; nt < 4; ++nt)
                    mma_tf32(c[mt][nt], af[mt], bf[nt]);
        }
        if (more) {
            int nb = buf ^ 1;
            As[nb][ac+0][ar0] = tf32_rna(pa0.x); As[nb][ac+1][ar0] = tf32_rna(pa0.y);
            As[nb][ac+2][ar0] = tf32_rna(pa0.z); As[nb][ac+3][ar0] = tf32_rna(pa0.w);
            As[nb][ac+0][ar0+64] = tf32_rna(pa1.x); As[nb][ac+1][ar0+64] = tf32_rna(pa1.y);
            As[nb][ac+2][ar0+64] = tf32_rna(pa1.z); As[nb][ac+3][ar0+64] = tf32_rna(pa1.w);
            Bs[nb][br0][bc+0]   = tf32_rna(pb0.x); Bs[nb][br0][bc+1]   = tf32_rna(pb0.y);
            Bs[nb][br0][bc+2]   = tf32_rna(pb0.z); Bs[nb][br0][bc+3]   = tf32_rna(pb0.w);
            Bs[nb][br0+8][bc+0] = tf32_rna(pb1.x); Bs[nb][br0+8][bc+1] = tf32_rna(pb1.y);
            Bs[nb][br0+8][bc+2] = tf32_rna(pb1.z); Bs[nb][br0+8][bc+3] = tf32_rna(pb1.w);
            __syncthreads();
            buf = nb;
        }
    }

    // ---------------- epilogue ----------------
    // warp's 32 columns live in one (s, head) block: bcol%128==0, n0%32==0
    int colbase = bcol + n0;
    int s  = colbase / NC;
    int hd = colbase - s * NC;
    int h  = hd >> 6;

    #pragma unroll
    for (int mt = 0; mt < 4; ++mt) {
        #pragma unroll
        for (int half = 0; half < 2; ++half) {
            int m = brow + m0 + mt * 16 + gid + half * 8;
            if (m >= MROWS) continue;
            float* dst = nullptr;
            int d_off = 0;
            if (SCATTER) {
                int b  = m / NTOK;
                int n  = m - b * NTOK;
                int bh = b * NHEAD + h;
                if (s == 0) {
                    dst = &g_q[((size_t)bh * NTOK + n) * ND];
                } else {
                    int dest = g_dest[bh * NTOK + n];
                    if (dest >= 0)
                        dst = &((s == 1) ? g_kp : g_vp)[((size_t)bh * NKEEP + dest) * ND];
                }
                d_off = hd & 63;        // head-local base dim for col n0
            } else {
                dst = out + (size_t)m * LDW + colbase;
            }
            if (!dst) continue;
            #pragma unroll
            for (int nt = 0; nt < 4; ++nt) {
                int cl = nt * 8 + tid4 * 2;        // 0..31 within warp block
                float2 bv = *(const float2*)(bias + colbase + cl);
                float2 o;
                o.x = c[mt][nt][half * 2 + 0] + bv.x;
                o.y = c[mt][nt][half * 2 + 1] + bv.y;
                *(float2*)(dst + (SCATTER ? d_off : 0) + cl) = o;
            }
        }
    }
}

// ---------------- attention: one CTA per (b,h, 32-query tile) -----------------
#define SS_STRIDE 292
#define KS_STRIDE 65
__global__ __launch_bounds__(256) void attn_kernel()
{
    extern __shared__ float sh[];
    float* Qs = sh;
    float* Vs = Qs + 32 * ND;
    float* Ss = Vs + NKEEP * ND;
    float* Ks = Ss + 32 * SS_STRIDE;

    int tid = threadIdx.x;
    int bh  = blockIdx.y;
    int q0  = blockIdx.x * 32;

    const float* kp = g_kp + (size_t)bh * NKEEP * ND;
    const float* vp = g_vp + (size_t)bh * NKEEP * ND;
    for (int idx = tid; idx < NKEEP * ND; idx += 256) {
        int m = idx >> 6, d = idx & 63;
        Ks[m * KS_STRIDE + d] = kp[idx];
        Vs[idx] = vp[idx];
    }
    const float* qp = g_q + (size_t)bh * NTOK * ND;
    for (int idx = tid; idx < 32 * ND; idx += 256) {
        int qq = idx >> 6;
        int qg = q0 + qq;
        Qs[idx] = (qg < NTOK) ? qp[(size_t)qg * ND + (idx & 63)] : 0.f;
    }
    __syncthreads();

    {
        int ty = tid >> 5, tx = tid & 31;
        #pragma unroll
        for (int pass = 0; pass < 3; ++pass) {
            int mb = pass * 128;
            int moff[4]; bool mv[4];
            #pragma unroll
            for (int j = 0; j < 4; ++j) {
                int m = mb + tx + 32 * j;
                mv[j] = (m < NKEEP);
                moff[j] = mv[j] ? m * KS_STRIDE : 0;
            }
            float acc[4][4];
            #pragma unroll
            for (int i = 0; i < 4; ++i)
                #pragma unroll
                for (int j = 0; j < 4; ++j) acc[i][j] = 0.f;
            for (int kk = 0; kk < ND; ++kk) {
                float a[4], bb[4];
                #pragma unroll
                for (int i = 0; i < 4; ++i) a[i] = Qs[(ty * 4 + i) * ND + kk];
                #pragma unroll
                for (int j = 0; j < 4; ++j) bb[j] = Ks[moff[j] + kk];
                #pragma unroll
                for (int i = 0; i < 4; ++i)
                    #pragma unroll
                    for (int j = 0; j < 4; ++j)
                        acc[i][j] = fmaf(a[i], bb[j], acc[i][j]);
            }
            #pragma unroll
            for (int j = 0; j < 4; ++j) {
                if (!mv[j]) continue;
                int m = mb + tx + 32 * j;
                #pragma unroll
                for (int i = 0; i < 4; ++i)
                    Ss[(ty * 4 + i) * SS_STRIDE + m] = acc[i][j] * 0.125f;
            }
        }
    }
    __syncthreads();

    {
        int w = tid >> 5, lane = tid & 31;
        #pragma unroll
        for (int r = 0; r < 4; ++r) {
            float* Sr = Ss + (w * 4 + r) * SS_STRIDE;
            float mx = -3.0e38f;
            for (int m = lane; m < NKEEP; m += 32) mx = fmaxf(mx, Sr[m]);
            #pragma unroll
            for (int o = 16; o; o >>= 1) mx = fmaxf(mx, __shfl_xor_sync(0xffffffffu, mx, o));
            float sum = 0.f;
            for (int m = lane; m < NKEEP; m += 32) {
                float e = __expf(Sr[m] - mx);
                Sr[m] = e;
                sum += e;
            }
            #pragma unroll
            for (int o = 16; o; o >>= 1) sum += __shfl_xor_sync(0xffffffffu, sum, o);
            float inv = 1.f / sum;
            for (int m = lane; m < NKEEP; m += 32) Sr[m] *= inv;
        }
    }
    __syncthreads();

    {
        int tx = tid & 15, ty = tid >> 4;
        float o0x=0.f,o0y=0.f,o0z=0.f,o0w=0.f;
        float o1x=0.f,o1y=0.f,o1z=0.f,o1w=0.f;
        int ql = ty * 2;
        const float* S0 = Ss + ql * SS_STRIDE;
        const float* S1 = S0 + SS_STRIDE;
        for (int m = 0; m < NKEEP; ++m) {
            float p0 = S0[m];
            float p1 = S1[m];
            float4 v = *(const float4*)&Vs[m * ND + tx * 4];
            o0x = fmaf(p0, v.x, o0x); o0y = fmaf(p0, v.y, o0y);
            o0z = fmaf(p0, v.z, o0z); o0w = fmaf(p0, v.w, o0w);
            o1x = fmaf(p1, v.x, o1x); o1y = fmaf(p1, v.y, o1y);
            o1z = fmaf(p1, v.z, o1z); o1w = fmaf(p1, v.w, o1w);
        }
        int b = bh / NHEAD, h = bh - b * NHEAD;
        int qg = q0 + ql;
        if (qg < NTOK)
            *(float4*)&g_ao[((size_t)(b * NTOK + qg)) * NC + h * ND + tx * 4]
                = make_float4(o0x, o0y, o0z, o0w);
        if (qg + 1 < NTOK)
            *(float4*)&g_ao[((size_t)(b * NTOK + qg + 1)) * NC + h * ND + tx * 4]
                = make_float4(o1x, o1y, o1z, o1w);
    }
}

// ---------------- launch -------------------------------------------------------
extern "C" void kernel_launch(void* const* d_in, const int* in_sizes, int n_in,
                              void* d_out, int out_size)
{
    const float* x     = (const float*)d_in[0];
    const float* mask  = (const float*)d_in[1];
    const float* Wqkv  = (const float*)d_in[2];
    const float* bqkv  = (const float*)d_in[3];
    const float* Wproj = (const float*)d_in[4];
    const float* bproj = (const float*)d_in[5];
    float* out = (float*)d_out;

    select_kernel<<<NB * NHEAD, 256>>>(mask);

    dim3 g1(QCOLS / 128, (MROWS + 127) / 128);
    gemm_mma<QCOLS, true, false><<<g1, 256>>>(x, Wqkv, bqkv, nullptr);

    size_t smem = (size_t)(32*ND + NKEEP*ND + 32*SS_STRIDE + NKEEP*KS_STRIDE) * sizeof(float);
    cudaFuncSetAttribute(attn_kernel, cudaFuncAttributeMaxDynamicSharedMemorySize, (int)smem);
    attn_kernel<<<dim3((NTOK + 31) / 32, NB * NHEAD), 256, smem>>>();

    dim3 g2(NC / 128, (MROWS + 127) / 128);
    gemm_mma<NC, false, true><<<g2, 256>>>(nullptr, Wproj, bproj, out);
}